// round 7
// baseline (speedup 1.0000x reference)
#include <cuda_runtime.h>
#include <cuda_bf16.h>
#include <cstdint>

#define BATCH 8192
#define TSTEPS 16
#define HID 512
#define FEAT 4
#define NGATE 2048  // 4*HID

// ---------------- static device scratch (no dynamic allocation) -------------
__device__ __nv_bfloat16 g_h16[3][BATCH * HID];              // h bf16: enc_s, enc_p, dec
__device__ float         g_h32[2][BATCH * HID];              // h fp32: enc_s, enc_p
__device__ float         g_cst[3][BATCH * HID];              // c fp32
__device__ __nv_bfloat16 g_W16[3][NGATE * HID];              // W_hh bf16
__device__ float         g_gates[2][(size_t)BATCH * NGATE];  // GEMM outputs
__device__ float         g_lastpos[BATCH * FEAT];

// ---------------- sm_80-level PTX helpers (base target sm_103: no tcgen05) --
static __device__ __forceinline__ uint32_t smem_u32(const void* p) {
    return (uint32_t)__cvta_generic_to_shared(p);
}
#define CP_ASYNC16(dst, src) \
    asm volatile("cp.async.cg.shared.global [%0], [%1], 16;" :: "r"(dst), "l"(src))
#define CP_COMMIT() asm volatile("cp.async.commit_group;" ::: "memory")
#define CP_WAIT0()  asm volatile("cp.async.wait_group 0;" ::: "memory")
#define CP_WAIT1()  asm volatile("cp.async.wait_group 1;" ::: "memory")

static __device__ __forceinline__ void ldsm_x4(uint32_t* r, uint32_t addr) {
    asm volatile("ldmatrix.sync.aligned.m8n8.x4.shared.b16 {%0,%1,%2,%3}, [%4];"
                 : "=r"(r[0]), "=r"(r[1]), "=r"(r[2]), "=r"(r[3]) : "r"(addr));
}
static __device__ __forceinline__ void ldsm_x2(uint32_t* r, uint32_t addr) {
    asm volatile("ldmatrix.sync.aligned.m8n8.x2.shared.b16 {%0,%1}, [%2];"
                 : "=r"(r[0]), "=r"(r[1]) : "r"(addr));
}
static __device__ __forceinline__ void mma_bf16(float* d, const uint32_t* a,
                                                const uint32_t* b) {
    asm volatile(
        "mma.sync.aligned.m16n8k16.row.col.f32.bf16.bf16.f32 "
        "{%0,%1,%2,%3}, {%4,%5,%6,%7}, {%8,%9}, {%0,%1,%2,%3};"
        : "+f"(d[0]), "+f"(d[1]), "+f"(d[2]), "+f"(d[3])
        : "r"(a[0]), "r"(a[1]), "r"(a[2]), "r"(a[3]), "r"(b[0]), "r"(b[1]));
}

// SW64 swizzle for 64-byte rows (BK=32 bf16).
static __device__ __forceinline__ uint32_t sw64(uint32_t off) {
    return off ^ ((off >> 3) & 0x30);
}

// ---------------------------------------------------------------------------
// GEMM: G[m,n] = sum_k A[m,k]*W[n,k]; A=[8192,512]bf16, W=[2048,512]bf16, G fp32
// CTA tile 128x128, BK=32, double-buffered cp.async, 8 warps (2x4), warp 64x32.
// mode 0: encoders (blockIdx.z picks s/p); mode 1: decoder.
// ---------------------------------------------------------------------------
__global__ void __launch_bounds__(256)
gemm_kernel(int mode)
{
    const __nv_bfloat16 *A, *W;
    float* G;
    if (mode == 0) {
        int e = blockIdx.z;
        A = g_h16[e]; W = g_W16[e]; G = g_gates[e];
    } else {
        A = g_h16[2]; W = g_W16[2]; G = g_gates[0];
    }

    const int n0 = blockIdx.x * 128;
    const int m0 = blockIdx.y * 128;
    const int tid  = threadIdx.x;
    const int lane = tid & 31;
    const int warp = tid >> 5;
    const int wm = warp >> 2;   // 0..1  (64-row band)
    const int wn = warp & 3;    // 0..3  (32-col band)

    // 2 stages x (A 8KB + B 8KB) = 32KB static smem
    __shared__ __align__(1024) unsigned char sm[32768];
    const uint32_t smBase = smem_u32(sm);

    const uint4* A4 = reinterpret_cast<const uint4*>(A);  // 8 bf16 per uint4
    const uint4* W4 = reinterpret_cast<const uint4*>(W);

    // cp.async mapping: 512 16B units per tile (128 rows x 4 units of 16B)
    const int cu  = tid & 3;           // 16B unit within 64B row
    const int cr0 = tid >> 2;          // rows 0..63 (i=0) and +64 (i=1)
    const uint32_t swoA0 = sw64((uint32_t)(cr0 * 64 + cu * 16));
    const uint32_t swoA1 = sw64((uint32_t)((cr0 + 64) * 64 + cu * 16));

    // ldmatrix addresses (offsets within a stage), per (frag, k16-step)
    uint32_t aOff[4][2], bOff[4][2];
    {
        int l = lane;
        #pragma unroll
        for (int fm = 0; fm < 4; ++fm) {
            int r = wm * 64 + fm * 16 + (l & 15);
            #pragma unroll
            for (int kk = 0; kk < 2; ++kk)
                aOff[fm][kk] = sw64((uint32_t)(r * 64 + kk * 32 + ((l >> 4) & 1) * 16));
        }
        int l2 = lane & 15;
        #pragma unroll
        for (int fn = 0; fn < 4; ++fn) {
            int r = wn * 32 + fn * 8 + (l2 & 7);
            #pragma unroll
            for (int kk = 0; kk < 2; ++kk)
                bOff[fn][kk] =
                    8192u + sw64((uint32_t)(r * 64 + kk * 32 + ((l2 >> 3) & 1) * 16));
        }
    }

    float d[4][4][4];
    #pragma unroll
    for (int i = 0; i < 4; ++i)
        #pragma unroll
        for (int j = 0; j < 4; ++j)
            #pragma unroll
            for (int q = 0; q < 4; ++q) d[i][j][q] = 0.0f;

    // ---- prologue: chunk 0 into stage 0
    {
        uint32_t st = smBase;
        CP_ASYNC16(st + swoA0,         (const void*)(A4 + (size_t)(m0 + cr0)      * 64 + cu));
        CP_ASYNC16(st + swoA1,         (const void*)(A4 + (size_t)(m0 + cr0 + 64) * 64 + cu));
        CP_ASYNC16(st + 8192u + swoA0, (const void*)(W4 + (size_t)(n0 + cr0)      * 64 + cu));
        CP_ASYNC16(st + 8192u + swoA1, (const void*)(W4 + (size_t)(n0 + cr0 + 64) * 64 + cu));
        CP_COMMIT();
    }

    for (int c = 0; c < 16; ++c) {
        if (c < 15) {
            uint32_t st = smBase + (uint32_t)(((c + 1) & 1) * 16384);
            int ko = (c + 1) * 4;   // uint4 offset along K (32 bf16 = 4 uint4)
            CP_ASYNC16(st + swoA0,         (const void*)(A4 + (size_t)(m0 + cr0)      * 64 + ko + cu));
            CP_ASYNC16(st + swoA1,         (const void*)(A4 + (size_t)(m0 + cr0 + 64) * 64 + ko + cu));
            CP_ASYNC16(st + 8192u + swoA0, (const void*)(W4 + (size_t)(n0 + cr0)      * 64 + ko + cu));
            CP_ASYNC16(st + 8192u + swoA1, (const void*)(W4 + (size_t)(n0 + cr0 + 64) * 64 + ko + cu));
            CP_COMMIT();
            CP_WAIT1();
        } else {
            CP_WAIT0();
        }
        __syncthreads();

        const uint32_t st = smBase + (uint32_t)((c & 1) * 16384);
        #pragma unroll
        for (int kk = 0; kk < 2; ++kk) {
            uint32_t a[4][4], b[4][2];
            #pragma unroll
            for (int fm = 0; fm < 4; ++fm) ldsm_x4(a[fm], st + aOff[fm][kk]);
            #pragma unroll
            for (int fn = 0; fn < 4; ++fn) ldsm_x2(b[fn], st + bOff[fn][kk]);
            #pragma unroll
            for (int fm = 0; fm < 4; ++fm)
                #pragma unroll
                for (int fn = 0; fn < 4; ++fn) mma_bf16(d[fm][fn], a[fm], b[fn]);
        }
        __syncthreads();   // compute done before this stage is refilled
    }

    // ---- epilogue: direct float2 stores
    #pragma unroll
    for (int fm = 0; fm < 4; ++fm) {
        int row = m0 + wm * 64 + fm * 16 + (lane >> 2);
        #pragma unroll
        for (int fn = 0; fn < 4; ++fn) {
            int col = n0 + wn * 32 + fn * 8 + (lane & 3) * 2;
            float2 v0 = make_float2(d[fm][fn][0], d[fm][fn][1]);
            float2 v1 = make_float2(d[fm][fn][2], d[fm][fn][3]);
            *reinterpret_cast<float2*>(G + (size_t)row * NGATE + col)       = v0;
            *reinterpret_cast<float2*>(G + (size_t)(row + 8) * NGATE + col) = v1;
        }
    }
}

// ---------------- pointwise --------------------------------------------------
static __device__ __forceinline__ float sigf(float x) { return 1.0f / (1.0f + expf(-x)); }

__global__ void __launch_bounds__(256)
prep_kernel(const float* __restrict__ Ws_hh, const float* __restrict__ Wp_hh,
            const float* __restrict__ Wd_hh)
{
    int lin = blockIdx.x * 256 + threadIdx.x;   // 0 .. BATCH*HID-1
    if (lin < NGATE * HID) {
        g_W16[0][lin] = __float2bfloat16(Ws_hh[lin]);
        g_W16[1][lin] = __float2bfloat16(Wp_hh[lin]);
        g_W16[2][lin] = __float2bfloat16(Wd_hh[lin]);
    }
    g_cst[0][lin] = 0.0f;
    g_cst[1][lin] = 0.0f;
}

__global__ void __launch_bounds__(256)
enc_pw_kernel(const float* __restrict__ speed, const float* __restrict__ pos,
              const float* __restrict__ Ws_ih, const float* __restrict__ bs_ih,
              const float* __restrict__ bs_hh,
              const float* __restrict__ Wp_ih, const float* __restrict__ bp_ih,
              const float* __restrict__ bp_hh, int t, int useG)
{
    const int enc = blockIdx.y;
    const float* x   = enc ? pos   : speed;
    const float* Wih = enc ? Wp_ih : Ws_ih;
    const float* bi  = enc ? bp_ih : bs_ih;
    const float* bh  = enc ? bp_hh : bs_hh;
    const float* G   = g_gates[enc];

    int lin = blockIdx.x * 256 + threadIdx.x;
    int b = lin >> 9, j = lin & 511;

    const float* xr = x + b * (TSTEPS * FEAT) + t * FEAT;
    float x0 = xr[0], x1 = xr[1], x2 = xr[2], x3 = xr[3];

    float gate[4];
    #pragma unroll
    for (int gi = 0; gi < 4; ++gi) {
        int n = j + gi * HID;
        const float* wr = Wih + n * 4;
        float g = useG ? G[(size_t)b * NGATE + n] : 0.0f;
        gate[gi] = g + bi[n] + bh[n] + x0 * wr[0] + x1 * wr[1] + x2 * wr[2] + x3 * wr[3];
    }
    float cold = g_cst[enc][lin];
    float cn = sigf(gate[1]) * cold + sigf(gate[0]) * tanhf(gate[2]);
    float h  = sigf(gate[3]) * tanhf(cn);
    g_cst[enc][lin] = cn;
    g_h32[enc][lin] = h;
    g_h16[enc][lin] = __float2bfloat16(h);
}

__global__ void __launch_bounds__(256)
combine_kernel(const float* __restrict__ pos)
{
    int lin = blockIdx.x * 256 + threadIdx.x;
    g_h16[2][lin] = __float2bfloat16(g_h32[0][lin] + g_h32[1][lin]);
    g_cst[2][lin] = g_cst[0][lin] + g_cst[1][lin];
    int b = lin >> 9, j = lin & 511;
    if (j < FEAT)
        g_lastpos[b * FEAT + j] = pos[b * (TSTEPS * FEAT) + (TSTEPS - 1) * FEAT + j];
}

__global__ void __launch_bounds__(512)
dec_pw_kernel(const float* __restrict__ Wd_ih, const float* __restrict__ bd_ih,
              const float* __restrict__ bd_hh,
              const float* __restrict__ W_fc, const float* __restrict__ b_fc,
              const float* __restrict__ W_emb, const float* __restrict__ b_emb,
              float* __restrict__ out, int t)
{
    const int b = blockIdx.x;
    const int j = threadIdx.x;
    float lp0 = g_lastpos[b * 4 + 0], lp1 = g_lastpos[b * 4 + 1];
    float lp2 = g_lastpos[b * 4 + 2], lp3 = g_lastpos[b * 4 + 3];
    const float* G = g_gates[0] + (size_t)b * NGATE;

    float gate[4];
    #pragma unroll
    for (int gi = 0; gi < 4; ++gi) {
        int n = j + gi * HID;
        const float* wr = Wd_ih + n * 4;
        gate[gi] = G[n] + bd_ih[n] + bd_hh[n]
                 + lp0 * wr[0] + lp1 * wr[1] + lp2 * wr[2] + lp3 * wr[3];
    }
    int lin = b * HID + j;
    float cold = g_cst[2][lin];
    float cn = sigf(gate[1]) * cold + sigf(gate[0]) * tanhf(gate[2]);
    float h  = sigf(gate[3]) * tanhf(cn);
    g_cst[2][lin] = cn;
    g_h16[2][lin] = __float2bfloat16(h);

    float s0 = h * W_fc[j];
    float s1 = h * W_fc[HID + j];
    #pragma unroll
    for (int off = 16; off > 0; off >>= 1) {
        s0 += __shfl_xor_sync(0xFFFFFFFFu, s0, off);
        s1 += __shfl_xor_sync(0xFFFFFFFFu, s1, off);
    }
    __shared__ float r0[16], r1[16];
    if ((j & 31) == 0) { r0[j >> 5] = s0; r1[j >> 5] = s1; }
    __syncthreads();
    if (j == 0) {
        float t0 = 0.f, t1 = 0.f;
        #pragma unroll
        for (int w = 0; w < 16; ++w) { t0 += r0[w]; t1 += r1[w]; }
        float c0 = fmaxf(t0 + b_fc[0], 0.f);
        float c1 = fmaxf(t1 + b_fc[1], 0.f);
        float m = fmaxf(c0, c1);
        float e0 = expf(c0 - m), e1 = expf(c1 - m);
        float inv = 1.f / (e0 + e1);
        out[((size_t)b * TSTEPS + t) * 2 + 0] = e0 * inv;
        out[((size_t)b * TSTEPS + t) * 2 + 1] = e1 * inv;
        #pragma unroll
        for (int k = 0; k < 4; ++k)
            g_lastpos[b * 4 + k] =
                fmaxf(c0 * W_emb[k * 2 + 0] + c1 * W_emb[k * 2 + 1] + b_emb[k], 0.f);
    }
}

// ---------------- orchestration ---------------------------------------------
extern "C" void kernel_launch(void* const* d_in, const int* in_sizes, int n_in,
                              void* d_out, int out_size)
{
    (void)in_sizes; (void)n_in; (void)out_size;
    const float* speed = (const float*)d_in[0];
    const float* pos   = (const float*)d_in[1];
    const float* Ws_ih = (const float*)d_in[2];
    const float* Ws_hh = (const float*)d_in[3];
    const float* bs_ih = (const float*)d_in[4];
    const float* bs_hh = (const float*)d_in[5];
    const float* Wp_ih = (const float*)d_in[6];
    const float* Wp_hh = (const float*)d_in[7];
    const float* bp_ih = (const float*)d_in[8];
    const float* bp_hh = (const float*)d_in[9];
    const float* Wd_ih = (const float*)d_in[10];
    const float* Wd_hh = (const float*)d_in[11];
    const float* bd_ih = (const float*)d_in[12];
    const float* bd_hh = (const float*)d_in[13];
    const float* W_fc  = (const float*)d_in[14];
    const float* b_fc  = (const float*)d_in[15];
    const float* W_emb = (const float*)d_in[16];
    const float* b_emb = (const float*)d_in[17];
    float* out = (float*)d_out;

    const int nPW = (BATCH * HID) / 256;   // 16384 blocks

    prep_kernel<<<nPW, 256>>>(Ws_hh, Wp_hh, Wd_hh);

    for (int t = 0; t < TSTEPS; ++t) {
        if (t > 0)
            gemm_kernel<<<dim3(NGATE / 128, BATCH / 128, 2), 256>>>(0);
        enc_pw_kernel<<<dim3(nPW, 2), 256>>>(speed, pos, Ws_ih, bs_ih, bs_hh,
                                             Wp_ih, bp_ih, bp_hh, t, t > 0 ? 1 : 0);
    }
    combine_kernel<<<nPW, 256>>>(pos);
    for (int t = 0; t < TSTEPS; ++t) {
        gemm_kernel<<<dim3(NGATE / 128, BATCH / 128, 1), 256>>>(1);
        dec_pw_kernel<<<BATCH, 512>>>(Wd_ih, bd_ih, bd_hh, W_fc, b_fc,
                                      W_emb, b_emb, out, t);
    }
}